// round 3
// baseline (speedup 1.0000x reference)
#include <cuda_runtime.h>

// LongConvolution2D via custom FFT (512x512 zero-padded rfft2 conv), fp32.
// y = unscaled_IDFT2( DFT2(x) * DFT2(filt) )[:256,:256] + x   (norm='forward')

#define BB 8
#define CC 64
#define HH 256
#define WW 256
#define NIMG (BB * CC)          // 512 images
#define NF 512                  // FFT length
#define NHALF 257               // NF/2 + 1

// Scratch (device globals; allocation-free per harness rules)
// g_xspec: [img][k2(257)][h(256)]  row-spectra of x, later overwritten with post-conv row-spectra
__device__ float2 g_xspec[(size_t)NIMG * NHALF * HH];   // ~269.5 MB
// g_kf: [c][k2(257)][k1(512)] full filter spectrum
__device__ float2 g_kf[(size_t)CC * NHALF * NF];        // ~67.4 MB
// g_frow: [c][k2(257)][h(256)] filter row-spectra (intermediate)
__device__ float2 g_frow[(size_t)CC * NHALF * HH];      // ~33.7 MB
// twiddle table: exp(-2*pi*i*j/512), j=0..255
__device__ float2 g_tw[256];

__device__ __forceinline__ float2 cmul(float2 a, float2 b) {
    return make_float2(a.x * b.x - a.y * b.y, a.x * b.y + a.y * b.x);
}
__device__ __forceinline__ int rev9(int i) { return (int)(__brev((unsigned)i) >> 23); }

// In-place 512-pt radix-2 DIT FFT. Data must be pre-placed in bit-reversed order.
// tw[j] = exp(-2*pi*i*j/512). INV=false: forward (e^-); INV=true: inverse (e^+), UNSCALED.
// 256 threads, t = threadIdx.x. Ends with __syncthreads().
// NOTE: __syncthreads() is at the TOP of each stage, BEFORE the tw read, so the
// caller's tw fill and sh pre-placement are both covered by the first barrier.
template <bool INV>
__device__ void fft512(float2* sh, const float2* tw, int t) {
#pragma unroll
    for (int len = 2; len <= 512; len <<= 1) {
        int half = len >> 1;
        int pos = t & (half - 1);
        int i = ((t - pos) << 1) + pos;   // group*len + pos
        int j = i + half;
        __syncthreads();                  // covers tw fill, pre-placement, prev stage
        float2 w = tw[pos * (512 / len)];
        if (INV) w.y = -w.y;
        float2 u = sh[i], v = sh[j];
        float2 vw = cmul(v, w);
        sh[i] = make_float2(u.x + vw.x, u.y + vw.y);
        sh[j] = make_float2(u.x - vw.x, u.y - vw.y);
    }
    __syncthreads();
}

__global__ void __launch_bounds__(256) k_init_tw() {
    int t = threadIdx.x;
    float s, c;
    sincosf(-6.283185307179586f * (float)t * (1.0f / 512.0f), &s, &c);
    g_tw[t] = make_float2(c, s);
}

// Row forward FFT (real 256 -> half spectrum 257) for x (FILT=false) or filt (FILT=true).
// One block per (img,row). Writes [img][k][h] (strided over k).
template <bool FILT>
__global__ void __launch_bounds__(256) k_row_fwd(const float* __restrict__ in) {
    __shared__ float2 sh[512];
    __shared__ float2 tw[256];
    int t = threadIdx.x;
    int bid = blockIdx.x;
    int img = bid >> 8;
    int h = bid & 255;
    tw[t] = g_tw[t];
    const float* row = in + ((size_t)img * HH + h) * WW;
    sh[rev9(t)] = make_float2(row[t], 0.0f);
    sh[rev9(t + 256)] = make_float2(0.0f, 0.0f);
    fft512<false>(sh, tw, t);
    float2* o = (FILT ? g_frow : g_xspec) + (size_t)img * (NHALF * HH) + h;
    o[(size_t)t * HH] = sh[t];
    if (t == 0) o[(size_t)256 * HH] = sh[256];
}

// Filter column forward FFT: for each (c, k2), 512-pt FFT of column (256 nonzero),
// store full 512 spectrum contiguously at g_kf[c][k2][*].
__global__ void __launch_bounds__(256) k_col_fwd_filt() {
    __shared__ float2 sh[512];
    __shared__ float2 tw[256];
    int t = threadIdx.x;
    int bid = blockIdx.x;
    int c = bid / NHALF;
    int k2 = bid - c * NHALF;
    tw[t] = g_tw[t];
    const float2* colin = g_frow + ((size_t)c * NHALF + k2) * HH;
    sh[rev9(t)] = colin[t];
    sh[rev9(t + 256)] = make_float2(0.0f, 0.0f);
    fft512<false>(sh, tw, t);
    float2* o = g_kf + ((size_t)c * NHALF + k2) * NF;
    o[t] = sh[t];
    o[t + 256] = sh[t + 256];
}

// Fused: forward column FFT of x-row-spectra, multiply by filter spectrum,
// inverse column FFT (unscaled), keep h<256, write back in place.
__global__ void __launch_bounds__(256) k_col_conv() {
    __shared__ float2 sh[512];
    __shared__ float2 tw[256];
    int t = threadIdx.x;
    int bid = blockIdx.x;
    int img = bid / NHALF;
    int k2 = bid - img * NHALF;
    int c = img & (CC - 1);
    tw[t] = g_tw[t];
    float2* col = g_xspec + ((size_t)img * NHALF + k2) * HH;
    sh[rev9(t)] = col[t];
    sh[rev9(t + 256)] = make_float2(0.0f, 0.0f);
    fft512<false>(sh, tw, t);
    const float2* kf = g_kf + ((size_t)c * NHALF + k2) * NF;
    float2 p0 = cmul(sh[t], kf[t]);
    float2 p1 = cmul(sh[t + 256], kf[t + 256]);
    __syncthreads();
    sh[rev9(t)] = p0;
    sh[rev9(t + 256)] = p1;
    fft512<true>(sh, tw, t);
    col[t] = sh[t];
}

// Row inverse: rebuild full 512 W-spectrum via hermitian symmetry, inverse FFT
// (unscaled), crop w<256, add residual x, write output.
__global__ void __launch_bounds__(256) k_row_inv(const float* __restrict__ x,
                                                 float* __restrict__ out) {
    __shared__ float2 sh[512];
    __shared__ float2 tw[256];
    int t = threadIdx.x;
    int bid = blockIdx.x;
    int img = bid >> 8;
    int h = bid & 255;
    tw[t] = g_tw[t];
    const float2* spec = g_xspec + (size_t)img * (NHALF * HH) + h;  // + k2*HH
    float2 a = spec[(size_t)t * HH];
    sh[rev9(t)] = a;
    if (t > 0) sh[rev9(512 - t)] = make_float2(a.x, -a.y);
    if (t == 0) {
        float2 b = spec[(size_t)256 * HH];
        sh[rev9(256)] = b;
    }
    fft512<true>(sh, tw, t);
    size_t idx = ((size_t)img * HH + h) * WW + t;
    out[idx] = sh[t].x + x[idx];
}

extern "C" void kernel_launch(void* const* d_in, const int* in_sizes, int n_in,
                              void* d_out, int out_size) {
    (void)in_sizes; (void)n_in; (void)out_size;
    const float* x = (const float*)d_in[0];
    const float* filt = (const float*)d_in[1];
    float* out = (float*)d_out;

    k_init_tw<<<1, 256>>>();
    // filter path (small): row FFTs then column FFTs -> full spectrum g_kf
    k_row_fwd<true><<<CC * HH, 256>>>(filt);
    k_col_fwd_filt<<<CC * NHALF, 256>>>();
    // x path: row FFTs -> fused col fwd * Kf * col inv -> row inverse + residual
    k_row_fwd<false><<<NIMG * HH, 256>>>(x);
    k_col_conv<<<NIMG * NHALF, 256>>>();
    k_row_inv<<<NIMG * HH, 256>>>(x, out);
}

// round 4
// speedup vs baseline: 5.1882x; 5.1882x over previous
#include <cuda_runtime.h>

// LongConvolution2D via custom radix-8 register FFT (512x512 zero-padded rfft2 conv), fp32.
// y = unscaled_IDFT2( DFT2(x) * DFT2(filt) )[:256,:256] + x   (norm='forward')

#define BB 8
#define CC 64
#define HH 256
#define WW 256
#define NIMG (BB * CC)          // 512 images
#define NF 512                  // FFT length
#define NHALF 257               // NF/2 + 1

#define SROW 68                 // padded scratch row stride (float2) for transposes
#define GSIZE 544               // per-group scratch size (float2), 8*68 = 544
#define TSTRIDE 5               // tile stride for [k][h4] staging tiles

// Scratch (device globals; allocation-free per harness rules)
__device__ __align__(256) float2 g_xspec[(size_t)NIMG * NHALF * HH];  // [img][k2][h] ~269.5MB
__device__ __align__(256) float2 g_kf[(size_t)CC * NHALF * NF];       // [c][k2][slot] scrambled
__device__ __align__(256) float2 g_frow[(size_t)CC * NHALF * HH];     // [c][k2][h]
__device__ __align__(256) float2 g_tw[256];                           // W512^j, j=0..255

__device__ __forceinline__ float2 f2add(float2 a, float2 b) { return make_float2(a.x + b.x, a.y + b.y); }
__device__ __forceinline__ float2 f2sub(float2 a, float2 b) { return make_float2(a.x - b.x, a.y - b.y); }
__device__ __forceinline__ float2 cmul(float2 a, float2 b) {
    return make_float2(a.x * b.x - a.y * b.y, a.x * b.y + a.y * b.x);
}
// multiply by -i (forward) or +i (inverse)
template <bool INV>
__device__ __forceinline__ float2 mul_mi(float2 v) {
    return INV ? make_float2(-v.y, v.x) : make_float2(v.y, -v.x);
}

template <bool INV>
__device__ __forceinline__ void dft4(float2& b0, float2& b1, float2& b2, float2& b3) {
    float2 s02 = f2add(b0, b2), d02 = f2sub(b0, b2);
    float2 s13 = f2add(b1, b3), d13 = mul_mi<INV>(f2sub(b1, b3));
    b0 = f2add(s02, s13); b2 = f2sub(s02, s13);
    b1 = f2add(d02, d13); b3 = f2sub(d02, d13);
}

// 8-point DFT, natural order in/out. Forward: W8 = e^{-2pi i/8}; INV: conjugated (unscaled).
template <bool INV>
__device__ __forceinline__ void dft8(float2 a[8]) {
    const float r = 0.70710678118654752440f;
    float2 u0 = f2add(a[0], a[4]), u1 = f2add(a[1], a[5]);
    float2 u2 = f2add(a[2], a[6]), u3 = f2add(a[3], a[7]);
    float2 v0 = f2sub(a[0], a[4]);
    float2 d1 = f2sub(a[1], a[5]), d2 = f2sub(a[2], a[6]), d3 = f2sub(a[3], a[7]);
    float2 v1 = INV ? make_float2(r * (d1.x - d1.y), r * (d1.x + d1.y))
                    : make_float2(r * (d1.x + d1.y), r * (d1.y - d1.x));
    float2 v2 = mul_mi<INV>(d2);
    float2 v3 = INV ? make_float2(-r * (d3.x + d3.y), r * (d3.x - d3.y))
                    : make_float2(r * (d3.y - d3.x), -r * (d3.x + d3.y));
    dft4<INV>(u0, u1, u2, u3);
    dft4<INV>(v0, v1, v2, v3);
    a[0] = u0; a[1] = v0; a[2] = u1; a[3] = v1;
    a[4] = u2; a[5] = v2; a[6] = u3; a[7] = v3;
}

// 512-point FFT, 64 threads per transform (t in [0,64)), 8 float2 per thread.
// Input:  a[r] = x[t + 64*r] (natural order).
// Output: a[j] = X[mout + 64*j], where mout = (t>>3) + 8*(t&7)  (bit-swapped t).
// s: per-group scratch of GSIZE float2. Uses __syncthreads() (all groups in lockstep).
template <bool INV>
__device__ void fft512_r8(float2 a[8], float2* s, int t) {
    // stage 1: DFT8 over r -> k2
    dft8<INV>(a);
    // twiddle a[k2] *= W512^{t*k2}
    {
        float2 w1 = g_tw[t];
        if (INV) w1.y = -w1.y;
        float2 w = w1;
        a[1] = cmul(a[1], w);
#pragma unroll
        for (int k = 2; k < 8; k++) { w = cmul(w, w1); a[k] = cmul(a[k], w); }
    }
    // transpose 1: s[k2][n1]
    __syncthreads();
#pragma unroll
    for (int k = 0; k < 8; k++) s[k * SROW + t] = a[k];
    __syncthreads();
    int u = t & 7, k2s = t >> 3;
#pragma unroll
    for (int v = 0; v < 8; v++) a[v] = s[k2s * SROW + u + 8 * v];
    // stage 2: DFT8 over v -> k1a
    dft8<INV>(a);
    // twiddle a[k1a] *= W64^{u*k1a}
    {
        float2 w2 = g_tw[8 * u];
        if (INV) w2.y = -w2.y;
        float2 w = w2;
        a[1] = cmul(a[1], w);
#pragma unroll
        for (int k = 2; k < 8; k++) { w = cmul(w, w2); a[k] = cmul(a[k], w); }
    }
    // transpose 2: s[k2][u][k1a]
    __syncthreads();
#pragma unroll
    for (int k = 0; k < 8; k++) s[k2s * SROW + 8 * u + k] = a[k];
    __syncthreads();
    int k1a = t & 7, k2f = t >> 3;
#pragma unroll
    for (int uu = 0; uu < 8; uu++) a[uu] = s[k2f * SROW + 8 * uu + k1a];
    // stage 3: DFT8 over u -> k1b
    dft8<INV>(a);
    // a[k1b] = X[k2f + 8*k1a + 64*k1b]
}

__device__ __forceinline__ int bswap6(int t) { return ((t & 7) << 3) | (t >> 3); }

__global__ void __launch_bounds__(256) k_init_tw() {
    int t = threadIdx.x;
    double ang = -6.283185307179586476925286766559 * (double)t / 512.0;
    double s, c;
    sincos(ang, &s, &c);
    g_tw[t] = make_float2((float)c, (float)s);
}

// Row forward FFT: 4 rows per block (4 groups of 64 threads). Real 256 input, zero-pad to 512.
// Output staged via smem tile -> coalesced [img][k][h] writes (k<=256 kept).
template <bool FILT>
__global__ void __launch_bounds__(256) k_row_fwd(const float* __restrict__ in) {
    __shared__ float2 sm[2176];
    int tid = threadIdx.x, g = tid >> 6, t = tid & 63;
    int img = blockIdx.x >> 6;
    int h0 = (blockIdx.x & 63) << 2;
    const float* row = in + ((size_t)img * HH + h0 + g) * WW;
    float2 a[8];
#pragma unroll
    for (int r = 0; r < 4; r++) a[r] = make_float2(row[t + 64 * r], 0.0f);
#pragma unroll
    for (int r = 4; r < 8; r++) a[r] = make_float2(0.0f, 0.0f);
    fft512_r8<false>(a, sm + g * GSIZE, t);
    __syncthreads();                 // scratch reads done in all groups; reuse smem as tile
    int m = bswap6(t);
#pragma unroll
    for (int j = 0; j < 4; j++) sm[(m + 64 * j) * TSTRIDE + g] = a[j];
    if (t == 0) sm[256 * TSTRIDE + g] = a[4];   // k = 256 (m=0, j=4)
    __syncthreads();
    float2* outb = (FILT ? g_frow : g_xspec) + (size_t)img * (NHALF * HH);
    for (int uu = tid; uu < 514; uu += 256) {
        int k = uu >> 1, hf = uu & 1;
        float2 p0 = sm[k * TSTRIDE + 2 * hf];
        float2 p1 = sm[k * TSTRIDE + 2 * hf + 1];
        *reinterpret_cast<float4*>(outb + (size_t)k * HH + h0 + 2 * hf) =
            make_float4(p0.x, p0.y, p1.x, p1.y);
    }
}

// Filter column forward FFT: 4 columns per block. Stores full scrambled spectrum
// (k1b-major slots) so k_col_conv can multiply with zero index math.
__global__ void __launch_bounds__(256) k_col_fwd_filt() {
    __shared__ float2 sm[2176];
    int tid = threadIdx.x, g = tid >> 6, t = tid & 63;
    int cid = blockIdx.x * 4 + g;          // 0 .. CC*NHALF-1
    int c = cid / NHALF, k2 = cid - c * NHALF;
    const float2* colin = g_frow + ((size_t)c * NHALF + k2) * HH;
    float2 a[8];
#pragma unroll
    for (int r = 0; r < 4; r++) a[r] = colin[t + 64 * r];
#pragma unroll
    for (int r = 4; r < 8; r++) a[r] = make_float2(0.0f, 0.0f);
    fft512_r8<false>(a, sm + g * GSIZE, t);
    float2* o = g_kf + ((size_t)c * NHALF + k2) * NF;
#pragma unroll
    for (int j = 0; j < 8; j++) o[j * 64 + t] = a[j];   // slot j*64+t holds K[bswap(t)+64j]
}

// Fused column conv: fwd FFT512 -> multiply by filter spectrum -> inverse FFT512 (unscaled),
// keep h<256, in place. 4 columns per block. No reordering needed between the two FFTs.
__global__ void __launch_bounds__(256) k_col_conv() {
    __shared__ float2 sm[2176];
    int tid = threadIdx.x, g = tid >> 6, t = tid & 63;
    int cid = blockIdx.x * 4 + g;          // 0 .. NIMG*NHALF-1
    int img = cid / NHALF, k2 = cid - img * NHALF;
    int c = img & (CC - 1);
    float2* col = g_xspec + ((size_t)img * NHALF + k2) * HH;
    float2 a[8];
#pragma unroll
    for (int r = 0; r < 4; r++) a[r] = col[t + 64 * r];
#pragma unroll
    for (int r = 4; r < 8; r++) a[r] = make_float2(0.0f, 0.0f);
    fft512_r8<false>(a, sm + g * GSIZE, t);
    // a[j] = X[bswap(t) + 64*j]; kf slot j*64+t holds K at identical index
    const float2* kf = g_kf + ((size_t)c * NHALF + k2) * NF;
#pragma unroll
    for (int j = 0; j < 8; j++) a[j] = cmul(a[j], kf[j * 64 + t]);
    // inverse: relabel thread as bswap(t); output comes back natural: a[j] = y[t + 64*j]
    fft512_r8<true>(a, sm + g * GSIZE, bswap6(t));
#pragma unroll
    for (int j = 0; j < 4; j++) col[t + 64 * j] = a[j];
}

// Row inverse: coalesced tile load of [k][h4] spectra, Hermitian reconstruction,
// inverse FFT512, crop w<256, residual add, coalesced float4 output.
__global__ void __launch_bounds__(256) k_row_inv(const float* __restrict__ x,
                                                 float* __restrict__ out) {
    __shared__ float2 sm[2176];
    float* rt = reinterpret_cast<float*>(sm);   // reused as real tile later
    int tid = threadIdx.x, g = tid >> 6, t = tid & 63;
    int img = blockIdx.x >> 6;
    int h0 = (blockIdx.x & 63) << 2;
    const float2* inb = g_xspec + (size_t)img * (NHALF * HH);
    for (int uu = tid; uu < 514; uu += 256) {
        int k = uu >> 1, hf = uu & 1;
        float4 v = *reinterpret_cast<const float4*>(inb + (size_t)k * HH + h0 + 2 * hf);
        sm[k * TSTRIDE + 2 * hf]     = make_float2(v.x, v.y);
        sm[k * TSTRIDE + 2 * hf + 1] = make_float2(v.z, v.w);
    }
    __syncthreads();
    float2 a[8];
#pragma unroll
    for (int r = 0; r < 8; r++) {
        int idx = t + 64 * r;
        if (idx <= 256) {
            a[r] = sm[idx * TSTRIDE + g];
        } else {
            float2 v = sm[(512 - idx) * TSTRIDE + g];
            a[r] = make_float2(v.x, -v.y);
        }
    }
    fft512_r8<true>(a, sm + g * GSIZE, t);   // leading sync inside protects tile reads
    __syncthreads();                         // all scratch reads done; reuse smem as rtile
    int m = bswap6(t);
#pragma unroll
    for (int j = 0; j < 4; j++) rt[g * 260 + m + 64 * j] = a[j].x;
    __syncthreads();
    int i = tid & 63, gg = tid >> 6;
    size_t rowoff = ((size_t)img * HH + h0 + gg) * WW;
    const float4* x4 = reinterpret_cast<const float4*>(x + rowoff);
    float4* o4 = reinterpret_cast<float4*>(out + rowoff);
    float4 yv = *reinterpret_cast<const float4*>(rt + gg * 260 + 4 * i);
    float4 xv = x4[i];
    o4[i] = make_float4(yv.x + xv.x, yv.y + xv.y, yv.z + xv.z, yv.w + xv.w);
}

extern "C" void kernel_launch(void* const* d_in, const int* in_sizes, int n_in,
                              void* d_out, int out_size) {
    (void)in_sizes; (void)n_in; (void)out_size;
    const float* x = (const float*)d_in[0];
    const float* filt = (const float*)d_in[1];
    float* out = (float*)d_out;

    k_init_tw<<<1, 256>>>();
    // filter path
    k_row_fwd<true><<<CC * 64, 256>>>(filt);
    k_col_fwd_filt<<<(CC * NHALF) / 4, 256>>>();
    // x path
    k_row_fwd<false><<<NIMG * 64, 256>>>(x);
    k_col_conv<<<(NIMG * NHALF) / 4, 256>>>();
    k_row_inv<<<NIMG * 64, 256>>>(x, out);
}

// round 5
// speedup vs baseline: 6.2928x; 1.2129x over previous
#include <cuda_runtime.h>

// LongConvolution2D via custom radix-8 register FFT (512x512 zero-padded rfft2 conv), fp32.
// y = unscaled_IDFT2( DFT2(x) * DFT2(filt) )[:256,:256] + x   (norm='forward')
// Row FFTs use the real-pair trick: two real rows per complex FFT.

#define BB 8
#define CC 64
#define HH 256
#define WW 256
#define NIMG (BB * CC)          // 512 images
#define NF 512                  // FFT length
#define NHALF 257               // NF/2 + 1

#define SROW 68                 // padded scratch row stride (float2) for transposes
#define GSIZE 544               // per-group scratch size (float2), 8*68 = 544
#define ZP 516                  // padded Z-tile stride (float2) per pair
#define RP 260                  // padded tile stride (float4 / float2 variants)

// Scratch (device globals; allocation-free per harness rules)
__device__ __align__(256) float2 g_xspec[(size_t)NIMG * NHALF * HH];  // [img][k2][h] ~269.5MB
__device__ __align__(256) float2 g_kf[(size_t)CC * NHALF * NF];       // [c][k2][slot] scrambled
__device__ __align__(256) float2 g_frow[(size_t)CC * NHALF * HH];     // [c][k2][h]
__device__ __align__(256) float2 g_tw[256];                           // W512^j, j=0..255

__device__ __forceinline__ float2 f2add(float2 a, float2 b) { return make_float2(a.x + b.x, a.y + b.y); }
__device__ __forceinline__ float2 f2sub(float2 a, float2 b) { return make_float2(a.x - b.x, a.y - b.y); }
__device__ __forceinline__ float2 cmul(float2 a, float2 b) {
    return make_float2(a.x * b.x - a.y * b.y, a.x * b.y + a.y * b.x);
}
// multiply by -i (forward) or +i (inverse)
template <bool INV>
__device__ __forceinline__ float2 mul_mi(float2 v) {
    return INV ? make_float2(-v.y, v.x) : make_float2(v.y, -v.x);
}

template <bool INV>
__device__ __forceinline__ void dft4(float2& b0, float2& b1, float2& b2, float2& b3) {
    float2 s02 = f2add(b0, b2), d02 = f2sub(b0, b2);
    float2 s13 = f2add(b1, b3), d13 = mul_mi<INV>(f2sub(b1, b3));
    b0 = f2add(s02, s13); b2 = f2sub(s02, s13);
    b1 = f2add(d02, d13); b3 = f2sub(d02, d13);
}

// 8-point DFT, natural order in/out. Forward: W8 = e^{-2pi i/8}; INV: conjugated (unscaled).
template <bool INV>
__device__ __forceinline__ void dft8(float2 a[8]) {
    const float r = 0.70710678118654752440f;
    float2 u0 = f2add(a[0], a[4]), u1 = f2add(a[1], a[5]);
    float2 u2 = f2add(a[2], a[6]), u3 = f2add(a[3], a[7]);
    float2 v0 = f2sub(a[0], a[4]);
    float2 d1 = f2sub(a[1], a[5]), d2 = f2sub(a[2], a[6]), d3 = f2sub(a[3], a[7]);
    float2 v1 = INV ? make_float2(r * (d1.x - d1.y), r * (d1.x + d1.y))
                    : make_float2(r * (d1.x + d1.y), r * (d1.y - d1.x));
    float2 v2 = mul_mi<INV>(d2);
    float2 v3 = INV ? make_float2(-r * (d3.x + d3.y), r * (d3.x - d3.y))
                    : make_float2(r * (d3.y - d3.x), -r * (d3.x + d3.y));
    dft4<INV>(u0, u1, u2, u3);
    dft4<INV>(v0, v1, v2, v3);
    a[0] = u0; a[1] = v0; a[2] = u1; a[3] = v1;
    a[4] = u2; a[5] = v2; a[6] = u3; a[7] = v3;
}

// 512-point FFT, 64 threads per transform (t in [0,64)), 8 float2 per thread.
// Input:  a[r] = x[t + 64*r] (natural order).
// Output: a[j] = X[mout + 64*j], where mout = (t>>3) + 8*(t&7)  (bit-swapped t).
// s: per-group scratch of GSIZE float2. Uses __syncthreads() (all groups in lockstep).
// The FIRST internal __syncthreads also orders any caller smem reads before scratch writes.
template <bool INV>
__device__ void fft512_r8(float2 a[8], float2* s, int t) {
    dft8<INV>(a);
    {
        float2 w1 = g_tw[t];
        if (INV) w1.y = -w1.y;
        float2 w = w1;
        a[1] = cmul(a[1], w);
#pragma unroll
        for (int k = 2; k < 8; k++) { w = cmul(w, w1); a[k] = cmul(a[k], w); }
    }
    __syncthreads();
#pragma unroll
    for (int k = 0; k < 8; k++) s[k * SROW + t] = a[k];
    __syncthreads();
    int u = t & 7, k2s = t >> 3;
#pragma unroll
    for (int v = 0; v < 8; v++) a[v] = s[k2s * SROW + u + 8 * v];
    dft8<INV>(a);
    {
        float2 w2 = g_tw[8 * u];
        if (INV) w2.y = -w2.y;
        float2 w = w2;
        a[1] = cmul(a[1], w);
#pragma unroll
        for (int k = 2; k < 8; k++) { w = cmul(w, w2); a[k] = cmul(a[k], w); }
    }
    __syncthreads();
#pragma unroll
    for (int k = 0; k < 8; k++) s[k2s * SROW + 8 * u + k] = a[k];
    __syncthreads();
    int k1a = t & 7, k2f = t >> 3;
#pragma unroll
    for (int uu = 0; uu < 8; uu++) a[uu] = s[k2f * SROW + 8 * uu + k1a];
    dft8<INV>(a);
    // a[k1b] = X[k2f + 8*k1a + 64*k1b]
}

__device__ __forceinline__ int bswap6(int t) { return ((t & 7) << 3) | (t >> 3); }

__global__ void __launch_bounds__(256) k_init_tw() {
    int t = threadIdx.x;
    double ang = -6.283185307179586476925286766559 * (double)t / 512.0;
    double s, c;
    sincos(ang, &s, &c);
    g_tw[t] = make_float2((float)c, (float)s);
}

// Row forward FFT, PAIRED: each 64-thread group does one pair of real rows as one
// complex FFT (z = row_even + i*row_odd). 4 groups/block -> 8 rows/block.
// Hermitian split folded into the smem staging tile; coalesced [img][k][h] writes.
template <bool FILT>
__global__ void __launch_bounds__(256) k_row_fwd(const float* __restrict__ in) {
    __shared__ float2 sm[2304];      // scratch (4*544) then Z-tile (4*516)
    int tid = threadIdx.x, g = tid >> 6, t = tid & 63;
    int img = blockIdx.x >> 5;
    int h0 = (blockIdx.x & 31) << 3;           // 8 rows per block
    const float* rowa = in + ((size_t)img * HH + h0 + 2 * g) * WW;
    const float* rowb = rowa + WW;
    float2 a[8];
#pragma unroll
    for (int r = 0; r < 4; r++) a[r] = make_float2(rowa[t + 64 * r], rowb[t + 64 * r]);
#pragma unroll
    for (int r = 4; r < 8; r++) a[r] = make_float2(0.0f, 0.0f);
    fft512_r8<false>(a, sm + g * GSIZE, t);
    __syncthreads();                 // scratch reads done in all groups; reuse smem as Z-tile
    int m = bswap6(t);
#pragma unroll
    for (int j = 0; j < 8; j++) sm[g * ZP + m + 64 * j] = a[j];
    __syncthreads();
    float2* outb = (FILT ? g_frow : g_xspec) + (size_t)img * (NHALF * HH);
    for (int uu = tid; uu < 4 * NHALF; uu += 256) {
        int k = uu >> 2, p = uu & 3;
        float2 Za = sm[p * ZP + k];
        float2 Zc = sm[p * ZP + ((512 - k) & 511)];
        float2 Xa = make_float2(0.5f * (Za.x + Zc.x), 0.5f * (Za.y - Zc.y));
        float2 Xb = make_float2(0.5f * (Za.y + Zc.y), 0.5f * (Zc.x - Za.x));
        *reinterpret_cast<float4*>(outb + (size_t)k * HH + h0 + 2 * p) =
            make_float4(Xa.x, Xa.y, Xb.x, Xb.y);
    }
}

// Filter column forward FFT: 4 columns per block. Stores full scrambled spectrum
// (k1b-major slots) so k_col_conv can multiply with zero index math.
__global__ void __launch_bounds__(256) k_col_fwd_filt() {
    __shared__ float2 sm[2304];
    int tid = threadIdx.x, g = tid >> 6, t = tid & 63;
    int cid = blockIdx.x * 4 + g;          // 0 .. CC*NHALF-1
    int c = cid / NHALF, k2 = cid - c * NHALF;
    const float2* colin = g_frow + ((size_t)c * NHALF + k2) * HH;
    float2 a[8];
#pragma unroll
    for (int r = 0; r < 4; r++) a[r] = colin[t + 64 * r];
#pragma unroll
    for (int r = 4; r < 8; r++) a[r] = make_float2(0.0f, 0.0f);
    fft512_r8<false>(a, sm + g * GSIZE, t);
    float2* o = g_kf + ((size_t)c * NHALF + k2) * NF;
#pragma unroll
    for (int j = 0; j < 8; j++) o[j * 64 + t] = a[j];   // slot j*64+t holds K[bswap(t)+64j]
}

// Fused column conv: fwd FFT512 -> multiply by filter spectrum -> inverse FFT512 (unscaled),
// keep h<256, in place. 4 columns per block. No reordering needed between the two FFTs.
__global__ void __launch_bounds__(256) k_col_conv() {
    __shared__ float2 sm[2304];
    int tid = threadIdx.x, g = tid >> 6, t = tid & 63;
    int cid = blockIdx.x * 4 + g;          // 0 .. NIMG*NHALF-1
    int img = cid / NHALF, k2 = cid - img * NHALF;
    int c = img & (CC - 1);
    float2* col = g_xspec + ((size_t)img * NHALF + k2) * HH;
    float2 a[8];
#pragma unroll
    for (int r = 0; r < 4; r++) a[r] = col[t + 64 * r];
#pragma unroll
    for (int r = 4; r < 8; r++) a[r] = make_float2(0.0f, 0.0f);
    fft512_r8<false>(a, sm + g * GSIZE, t);
    const float2* kf = g_kf + ((size_t)c * NHALF + k2) * NF;
#pragma unroll
    for (int j = 0; j < 8; j++) a[j] = cmul(a[j], kf[j * 64 + t]);
    fft512_r8<true>(a, sm + g * GSIZE, bswap6(t));   // output natural: a[j] = y[t + 64*j]
#pragma unroll
    for (int j = 0; j < 4; j++) col[t + 64 * j] = a[j];
}

// Row inverse, PAIRED: two Hermitian spectra per complex inverse FFT.
// Coalesced float4 tile load builds Sa,Sb; Z = Sa + i*Sb formed in registers;
// y_even = Re, y_odd = Im; crop w<256, residual add, coalesced float4 output.
__global__ void __launch_bounds__(256) k_row_inv(const float* __restrict__ x,
                                                 float* __restrict__ out) {
    __shared__ float2 sm[2304];
    float4* tile4 = reinterpret_cast<float4*>(sm);   // [pair][k] pad RP (1040 float4)
    int tid = threadIdx.x, g = tid >> 6, t = tid & 63;
    int img = blockIdx.x >> 5;
    int h0 = (blockIdx.x & 31) << 3;
    const float2* inb = g_xspec + (size_t)img * (NHALF * HH);
    for (int uu = tid; uu < 4 * NHALF; uu += 256) {
        int k = uu >> 2, p = uu & 3;
        tile4[p * RP + k] =
            *reinterpret_cast<const float4*>(inb + (size_t)k * HH + h0 + 2 * p);
    }
    __syncthreads();
    float2 a[8];
#pragma unroll
    for (int r = 0; r < 8; r++) {
        int idx = t + 64 * r;
        if (idx <= 256) {
            float4 v = tile4[g * RP + idx];          // Sa=(v.x,v.y) Sb=(v.z,v.w)
            a[r] = make_float2(v.x - v.w, v.y + v.z);
        } else {
            float4 w = tile4[g * RP + (512 - idx)];
            a[r] = make_float2(w.x + w.w, w.z - w.y);
        }
    }
    fft512_r8<true>(a, sm + g * GSIZE, t);   // first internal sync protects tile reads
    __syncthreads();                          // scratch reads done; reuse smem as y-tile
    int m = bswap6(t);
#pragma unroll
    for (int j = 0; j < 4; j++) sm[g * RP + m + 64 * j] = a[j];  // (y_even, y_odd)
    __syncthreads();
    int i = tid & 63, r8 = tid >> 6;          // r8 = row 0..3 of first 4; loop twice
#pragma unroll
    for (int rr = 0; rr < 2; rr++) {
        int row = r8 + 4 * rr;                // 0..7
        int p = row >> 1, e = row & 1;
        size_t rowoff = ((size_t)img * HH + h0 + row) * WW;
        const float4* x4 = reinterpret_cast<const float4*>(x + rowoff);
        const float2* yt = sm + p * RP + 4 * i;
        float4 xv = x4[i];
        float4 ov;
        if (e == 0) ov = make_float4(yt[0].x + xv.x, yt[1].x + xv.y,
                                     yt[2].x + xv.z, yt[3].x + xv.w);
        else        ov = make_float4(yt[0].y + xv.x, yt[1].y + xv.y,
                                     yt[2].y + xv.z, yt[3].y + xv.w);
        reinterpret_cast<float4*>(out + rowoff)[i] = ov;
    }
}

extern "C" void kernel_launch(void* const* d_in, const int* in_sizes, int n_in,
                              void* d_out, int out_size) {
    (void)in_sizes; (void)n_in; (void)out_size;
    const float* x = (const float*)d_in[0];
    const float* filt = (const float*)d_in[1];
    float* out = (float*)d_out;

    k_init_tw<<<1, 256>>>();
    // filter path
    k_row_fwd<true><<<CC * 32, 256>>>(filt);
    k_col_fwd_filt<<<(CC * NHALF) / 4, 256>>>();
    // x path
    k_row_fwd<false><<<NIMG * 32, 256>>>(x);
    k_col_conv<<<(NIMG * NHALF) / 4, 256>>>();
    k_row_inv<<<NIMG * 32, 256>>>(x, out);
}

// round 7
// speedup vs baseline: 9.5217x; 1.5131x over previous
#include <cuda_runtime.h>

// LongConvolution2D via custom radix-8 register FFT (512x512 zero-padded rfft2 conv), fp32.
// y = unscaled_IDFT2( DFT2(x) * DFT2(filt) )[:256,:256] + x   (norm='forward')
// Row FFTs use the real-pair trick. All shared-memory layouts bank-conflict-free.

#define BB 8
#define CC 64
#define HH 256
#define WW 256
#define NIMG (BB * CC)          // 512 images
#define NF 512                  // FFT length
#define NHALF 257               // NF/2 + 1

#define GS 584                  // per-group scratch (float2): 8 * max(SROW)=8*73
#define ZT 550                  // Z-tile per-pair stride (float2), skewed natural-slot layout
#define RPI 258                 // input tile per-pair stride (float4)
#define RPY 312                 // y-tile per-pair stride (float2)
#define SMSZ 2336               // block smem (float2): 4*GS

// Scratch (device globals; allocation-free per harness rules)
__device__ __align__(256) float2 g_xspec[(size_t)NIMG * NHALF * HH];  // [img][k2][h] ~269.5MB
__device__ __align__(256) float2 g_kf[(size_t)CC * NHALF * NF];       // [c][k2][slot] scrambled
__device__ __align__(256) float2 g_frow[(size_t)CC * NHALF * HH];     // [c][k2][h]
__device__ __align__(256) float2 g_tw[256];                           // W512^j, j=0..255

__device__ __forceinline__ float2 f2add(float2 a, float2 b) { return make_float2(a.x + b.x, a.y + b.y); }
__device__ __forceinline__ float2 f2sub(float2 a, float2 b) { return make_float2(a.x - b.x, a.y - b.y); }
__device__ __forceinline__ float2 cmul(float2 a, float2 b) {
    return make_float2(a.x * b.x - a.y * b.y, a.x * b.y + a.y * b.x);
}
template <bool INV>
__device__ __forceinline__ float2 mul_mi(float2 v) {
    return INV ? make_float2(-v.y, v.x) : make_float2(v.y, -v.x);
}

template <bool INV>
__device__ __forceinline__ void dft4(float2& b0, float2& b1, float2& b2, float2& b3) {
    float2 s02 = f2add(b0, b2), d02 = f2sub(b0, b2);
    float2 s13 = f2add(b1, b3), d13 = mul_mi<INV>(f2sub(b1, b3));
    b0 = f2add(s02, s13); b2 = f2sub(s02, s13);
    b1 = f2add(d02, d13); b3 = f2sub(d02, d13);
}

template <bool INV>
__device__ __forceinline__ void dft8(float2 a[8]) {
    const float r = 0.70710678118654752440f;
    float2 u0 = f2add(a[0], a[4]), u1 = f2add(a[1], a[5]);
    float2 u2 = f2add(a[2], a[6]), u3 = f2add(a[3], a[7]);
    float2 v0 = f2sub(a[0], a[4]);
    float2 d1 = f2sub(a[1], a[5]), d2 = f2sub(a[2], a[6]), d3 = f2sub(a[3], a[7]);
    float2 v1 = INV ? make_float2(r * (d1.x - d1.y), r * (d1.x + d1.y))
                    : make_float2(r * (d1.x + d1.y), r * (d1.y - d1.x));
    float2 v2 = mul_mi<INV>(d2);
    float2 v3 = INV ? make_float2(-r * (d3.x + d3.y), r * (d3.x - d3.y))
                    : make_float2(r * (d3.y - d3.x), -r * (d3.x + d3.y));
    dft4<INV>(u0, u1, u2, u3);
    dft4<INV>(v0, v1, v2, v3);
    a[0] = u0; a[1] = v0; a[2] = u1; a[3] = v1;
    a[4] = u2; a[5] = v2; a[6] = u3; a[7] = v3;
}

__device__ __forceinline__ int bswap6(int t) { return ((t & 7) << 3) | (t >> 3); }

// 512-point FFT, 64 threads per transform, 8 float2 per thread.
// t = LOGICAL thread label. Input: a[r] = x[t + 64*r]. Output: a[j] = X[bswap6(t) + 64*j].
// PERM=true is for calls where the physical lane holds logical label bswap6(lane):
// T1 stores sample n1 at column bswap6(n1) so physical addressing stays conflict-free.
// SR / C2: scratch strides chosen per-instantiation for bank-conflict freedom:
//   natural calls: SR=72, C2=9;  PERM calls: SR=73, C2=8.
template <bool INV, bool PERM, int SR, int C2>
__device__ void fft512_r8(float2 a[8], float2* s, int t) {
    dft8<INV>(a);
    {
        float2 w1 = g_tw[t];
        if (INV) w1.y = -w1.y;
        float2 w = w1;
        a[1] = cmul(a[1], w);
#pragma unroll
        for (int k = 2; k < 8; k++) { w = cmul(w, w1); a[k] = cmul(a[k], w); }
    }
    __syncthreads();                  // orders caller smem reads + prev stage
    int col = PERM ? bswap6(t) : t;
#pragma unroll
    for (int k = 0; k < 8; k++) s[k * SR + col] = a[k];
    __syncthreads();
    int u = t & 7, k2s = t >> 3;
#pragma unroll
    for (int v = 0; v < 8; v++)
        a[v] = s[k2s * SR + (PERM ? (8 * u + v) : (u + 8 * v))];
    dft8<INV>(a);
    {
        float2 w2 = g_tw[8 * u];
        if (INV) w2.y = -w2.y;
        float2 w = w2;
        a[1] = cmul(a[1], w);
#pragma unroll
        for (int k = 2; k < 8; k++) { w = cmul(w, w2); a[k] = cmul(a[k], w); }
    }
    __syncthreads();
#pragma unroll
    for (int k = 0; k < 8; k++) s[k2s * SR + C2 * k + u] = a[k];
    __syncthreads();
    int k1a = t & 7, k2f = t >> 3;
#pragma unroll
    for (int uu = 0; uu < 8; uu++) a[uu] = s[k2f * SR + C2 * k1a + uu];
    dft8<INV>(a);
    // a[k1b] = X[k2f + 8*k1a + 64*k1b] = X[bswap6(t) + 64*k1b]
}

__global__ void __launch_bounds__(256) k_init_tw() {
    int t = threadIdx.x;
    double ang = -6.283185307179586476925286766559 * (double)t / 512.0;
    double s, c;
    sincos(ang, &s, &c);
    g_tw[t] = make_float2((float)c, (float)s);
}

// Row forward FFT, PAIRED: z = row_even + i*row_odd, one complex FFT per pair.
// Z staged in natural-slot skewed tile (conflict-free), Hermitian split on read,
// coalesced float4 writes to [img][k][h].
template <bool FILT>
__global__ void __launch_bounds__(256) k_row_fwd(const float* __restrict__ in) {
    __shared__ float2 sm[SMSZ];
    int tid = threadIdx.x, g = tid >> 6, t = tid & 63;
    int img = blockIdx.x >> 5;
    int h0 = (blockIdx.x & 31) << 3;
    const float* rowa = in + ((size_t)img * HH + h0 + 2 * g) * WW;
    const float* rowb = rowa + WW;
    float2 a[8];
#pragma unroll
    for (int r = 0; r < 4; r++) a[r] = make_float2(rowa[t + 64 * r], rowb[t + 64 * r]);
#pragma unroll
    for (int r = 4; r < 8; r++) a[r] = make_float2(0.0f, 0.0f);
    fft512_r8<false, false, 72, 9>(a, sm + g * GS, t);
    __syncthreads();                 // scratch reads done in all groups; reuse smem as Z-tile
#pragma unroll
    for (int j = 0; j < 8; j++) {
        int slot = t + 64 * j;
        sm[g * ZT + slot + (slot >> 4)] = a[j];   // Z[bswap6(slot&63) + 64*(slot>>6)]
    }
    __syncthreads();
    float2* outb = (FILT ? g_frow : g_xspec) + (size_t)img * (NHALF * HH);
    for (int uu = tid; uu < 4 * NHALF; uu += 256) {
        int k = uu >> 2, p = uu & 3;
        int kc = (512 - k) & 511;
        int sa = bswap6(k & 63) + (k & 448);  sa += sa >> 4;
        int sc = bswap6(kc & 63) + (kc & 448); sc += sc >> 4;
        float2 Za = sm[p * ZT + sa];
        float2 Zc = sm[p * ZT + sc];
        float2 Xa = make_float2(0.5f * (Za.x + Zc.x), 0.5f * (Za.y - Zc.y));
        float2 Xb = make_float2(0.5f * (Za.y + Zc.y), 0.5f * (Zc.x - Za.x));
        *reinterpret_cast<float4*>(outb + (size_t)k * HH + h0 + 2 * p) =
            make_float4(Xa.x, Xa.y, Xb.x, Xb.y);
    }
}

// Filter column forward FFT: stores full scrambled spectrum (slot j*64+t).
__global__ void __launch_bounds__(256) k_col_fwd_filt() {
    __shared__ float2 sm[SMSZ];
    int tid = threadIdx.x, g = tid >> 6, t = tid & 63;
    int cid = blockIdx.x * 4 + g;
    int c = cid / NHALF, k2 = cid - c * NHALF;
    const float2* colin = g_frow + ((size_t)c * NHALF + k2) * HH;
    float2 a[8];
#pragma unroll
    for (int r = 0; r < 4; r++) a[r] = colin[t + 64 * r];
#pragma unroll
    for (int r = 4; r < 8; r++) a[r] = make_float2(0.0f, 0.0f);
    fft512_r8<false, false, 72, 9>(a, sm + g * GS, t);
    float2* o = g_kf + ((size_t)c * NHALF + k2) * NF;
#pragma unroll
    for (int j = 0; j < 8; j++) o[j * 64 + t] = a[j];
}

// Fused column conv: fwd FFT -> multiply -> inverse FFT (PERM instantiation keeps
// all physical smem addressing conflict-free), keep h<256, in place.
__global__ void __launch_bounds__(256) k_col_conv() {
    __shared__ float2 sm[SMSZ];
    int tid = threadIdx.x, g = tid >> 6, t = tid & 63;
    int cid = blockIdx.x * 4 + g;
    int img = cid / NHALF, k2 = cid - img * NHALF;
    int c = img & (CC - 1);
    float2* col = g_xspec + ((size_t)img * NHALF + k2) * HH;
    float2 a[8];
#pragma unroll
    for (int r = 0; r < 4; r++) a[r] = col[t + 64 * r];
#pragma unroll
    for (int r = 4; r < 8; r++) a[r] = make_float2(0.0f, 0.0f);
    fft512_r8<false, false, 72, 9>(a, sm + g * GS, t);
    const float2* kf = g_kf + ((size_t)c * NHALF + k2) * NF;
#pragma unroll
    for (int j = 0; j < 8; j++) a[j] = cmul(a[j], kf[j * 64 + t]);
    fft512_r8<true, true, 73, 8>(a, sm + g * GS, bswap6(t));  // out: a[j] = y[t + 64*j]
#pragma unroll
    for (int j = 0; j < 4; j++) col[t + 64 * j] = a[j];
}

// Row inverse, PAIRED: Z = Sa + i*Sb from coalesced float4 tile; inverse FFT;
// y_even = Re, y_odd = Im via skewed natural-slot tile; residual add; float4 out.
__global__ void __launch_bounds__(256) k_row_inv(const float* __restrict__ x,
                                                 float* __restrict__ out) {
    __shared__ float2 sm[SMSZ];
    float4* tile4 = reinterpret_cast<float4*>(sm);
    int tid = threadIdx.x, g = tid >> 6, t = tid & 63;
    int img = blockIdx.x >> 5;
    int h0 = (blockIdx.x & 31) << 3;
    const float2* inb = g_xspec + (size_t)img * (NHALF * HH);
    for (int uu = tid; uu < 4 * NHALF; uu += 256) {
        int k = uu >> 2, p = uu & 3;
        tile4[p * RPI + k] =
            *reinterpret_cast<const float4*>(inb + (size_t)k * HH + h0 + 2 * p);
    }
    __syncthreads();
    float2 a[8];
#pragma unroll
    for (int r = 0; r < 8; r++) {
        int idx = t + 64 * r;
        if (idx <= 256) {
            float4 v = tile4[g * RPI + idx];          // Sa=(x,y) Sb=(z,w)
            a[r] = make_float2(v.x - v.w, v.y + v.z);
        } else {
            float4 w = tile4[g * RPI + (512 - idx)];
            a[r] = make_float2(w.x + w.w, w.z - w.y);
        }
    }
    fft512_r8<true, false, 72, 9>(a, sm + g * GS, t);  // first internal sync guards tile reads
    __syncthreads();                                    // scratch done; reuse smem as y-tile
#pragma unroll
    for (int j = 0; j < 4; j++) {
        int slot = t + 64 * j;
        sm[g * RPY + slot + 8 * (slot >> 5)] = a[j];    // y[bswap6(slot&63)+64*(slot>>6)]
    }
    __syncthreads();
    int i = tid & 63, r8 = tid >> 6;
#pragma unroll
    for (int rr = 0; rr < 2; rr++) {
        int row = r8 + 4 * rr;
        int p = row >> 1, e = row & 1;
        size_t rowoff = ((size_t)img * HH + h0 + row) * WW;
        float4 xv = reinterpret_cast<const float4*>(x + rowoff)[i];
        float y[4];
#pragma unroll
        for (int cc = 0; cc < 4; cc++) {
            int w = 4 * i + cc;
            int sl = bswap6(w & 63) + (w & 192);
            sl += 8 * (sl >> 5);
            float2 yv = sm[p * RPY + sl];
            y[cc] = e ? yv.y : yv.x;
        }
        reinterpret_cast<float4*>(out + rowoff)[i] =
            make_float4(y[0] + xv.x, y[1] + xv.y, y[2] + xv.z, y[3] + xv.w);
    }
}

extern "C" void kernel_launch(void* const* d_in, const int* in_sizes, int n_in,
                              void* d_out, int out_size) {
    (void)in_sizes; (void)n_in; (void)out_size;
    const float* x = (const float*)d_in[0];
    const float* filt = (const float*)d_in[1];
    float* out = (float*)d_out;

    k_init_tw<<<1, 256>>>();
    // filter path
    k_row_fwd<true><<<CC * 32, 256>>>(filt);
    k_col_fwd_filt<<<(CC * NHALF) / 4, 256>>>();
    // x path
    k_row_fwd<false><<<NIMG * 32, 256>>>(x);
    k_col_conv<<<(NIMG * NHALF) / 4, 256>>>();
    k_row_inv<<<NIMG * 32, 256>>>(x, out);
}